// round 12
// baseline (speedup 1.0000x reference)
#include <cuda_runtime.h>
#include <cuda_bf16.h>
#include <math.h>

// Problem constants
#define BATCH 8
#define MDIM 256
#define NDIM 256
#define DDIM 512
#define NDIAG 511            // M + N - 1
#define NDPAD 512            // padded diag count (g_W only)
#define INFV 100000000.0f    // matches reference _INF
#define GAMMA_MIN 0.0001f

// ---------------------------------------------------------------------------
// Scratch (static device globals; no allocation)
// layout: diag-major  [b][d][i]  with i = row index (global m), d = m + n
// ---------------------------------------------------------------------------
__device__ float  g_rx[BATCH * MDIM];                 // 1/||x_m||
__device__ float  g_ry[BATCH * NDIM];                 // 1/||y_n||
__device__ float  g_cost[BATCH * NDIAG * MDIM];       // cost, diag-major
__device__ float  g_R[BATCH * NDIAG * MDIM];          // R (interior), diag-major
__device__ float  g_S[BATCH * NDIAG * MDIM];          // softmin value (= R - cost)
__device__ float4 g_W[BATCH * NDPAD * MDIM];          // (wd, wn, wr, seed) per cell
__device__ float  g_E[BATCH * NDIAG * MDIM];          // alignment, diag-major

__device__ __forceinline__ float clamp50(float v)
{
    return fminf(fmaxf(v, -50.0f), 50.0f);
}

__device__ __forceinline__ float ex2_(float x)       // MUFU.EX2
{
    float r;
    asm("ex2.approx.f32 %0, %1;" : "=f"(r) : "f"(x));
    return r;
}
__device__ __forceinline__ float lg2_(float x)       // MUFU.LG2
{
    float r;
    asm("lg2.approx.f32 %0, %1;" : "=f"(r) : "f"(x));
    return r;
}

// softmin_3 via exp2/log2 with folded constants
__device__ __forceinline__ float softmin3(float a, float b, float c,
                                          float ig2, float gl)
{
    float mn = fminf(a, fminf(b, c));
    float s  = ex2_((mn - a) * ig2)
             + ex2_((mn - b) * ig2)
             + ex2_((mn - c) * ig2);
    return mn - gl * lg2_(s);
}

// acquire/release on CTA-shared memory (cross-warp mailbox ordering)
__device__ __forceinline__ void st_release_cta(int* p, int v)
{
    unsigned a = (unsigned)__cvta_generic_to_shared(p);
    asm volatile("st.release.cta.shared.b32 [%0], %1;" :: "r"(a), "r"(v) : "memory");
}
__device__ __forceinline__ int ld_acquire_cta(const int* p)
{
    unsigned a = (unsigned)__cvta_generic_to_shared((void*)p);
    int v;
    asm volatile("ld.acquire.cta.shared.b32 %0, [%1];" : "=r"(v) : "r"(a) : "memory");
    return v;
}

// ---------------------------------------------------------------------------
// Kernel 1: inverse row norms for x and y.  One warp per row.
// ---------------------------------------------------------------------------
__global__ __launch_bounds__(256) void norms_kernel(const float* __restrict__ x,
                                                    const float* __restrict__ y)
{
    int warp = threadIdx.x >> 5;
    int lane = threadIdx.x & 31;
    int row  = blockIdx.x * 8 + warp;          // 512 blocks * 8 warps = 4096 rows

    const float* base;
    float* out;
    if (row < BATCH * MDIM) {
        base = x + (size_t)row * DDIM;
        out  = g_rx + row;
    } else {
        int r = row - BATCH * MDIM;
        base = y + (size_t)r * DDIM;
        out  = g_ry + r;
    }

    const float4* b4 = reinterpret_cast<const float4*>(base);
    float s = 0.0f;
#pragma unroll
    for (int t = 0; t < 4; ++t) {
        float4 v = b4[lane + 32 * t];
        s += v.x * v.x + v.y * v.y + v.z * v.z + v.w * v.w;
    }
#pragma unroll
    for (int o = 16; o; o >>= 1) s += __shfl_xor_sync(0xFFFFFFFFu, s, o);

    if (lane == 0) {
        float n = sqrtf(s);
        n = fmaxf(n, 1e-8f);
        *out = 1.0f / n;
    }
}

// ---------------------------------------------------------------------------
// Kernel 2: cost = 1 - (x.y) * rx * ry, written DIAG-MAJOR.
// ---------------------------------------------------------------------------
#define BM 64
#define BN 64
#define BK 16

__global__ __launch_bounds__(256) void cost_kernel(const float* __restrict__ x,
                                                   const float* __restrict__ y)
{
    __shared__ float Xs[BK][BM + 1];
    __shared__ float Ys[BK][BN + 1];

    int b  = blockIdx.z;
    int m0 = blockIdx.y * BM;
    int n0 = blockIdx.x * BN;
    int tx = threadIdx.x;
    int ty = threadIdx.y;
    int tid = ty * 16 + tx;

    const float* xb = x + ((size_t)b * MDIM + m0) * DDIM;
    const float* yb = y + ((size_t)b * NDIM + n0) * DDIM;

    float acc[4][4];
#pragma unroll
    for (int r = 0; r < 4; ++r)
#pragma unroll
        for (int c = 0; c < 4; ++c) acc[r][c] = 0.0f;

    int kk = tid & 15;
    int rr = tid >> 4;

    for (int k0 = 0; k0 < DDIM; k0 += BK) {
#pragma unroll
        for (int r = 0; r < 4; ++r) {
            Xs[kk][rr + r * 16] = xb[(size_t)(rr + r * 16) * DDIM + k0 + kk];
            Ys[kk][rr + r * 16] = yb[(size_t)(rr + r * 16) * DDIM + k0 + kk];
        }
        __syncthreads();
#pragma unroll
        for (int k = 0; k < BK; ++k) {
            float a[4], bv[4];
#pragma unroll
            for (int r = 0; r < 4; ++r) a[r]  = Xs[k][ty * 4 + r];
#pragma unroll
            for (int c = 0; c < 4; ++c) bv[c] = Ys[k][tx * 4 + c];
#pragma unroll
            for (int r = 0; r < 4; ++r)
#pragma unroll
                for (int c = 0; c < 4; ++c) acc[r][c] += a[r] * bv[c];
        }
        __syncthreads();
    }

    float* costb = g_cost + (size_t)b * NDIAG * MDIM;
#pragma unroll
    for (int r = 0; r < 4; ++r) {
        int row = m0 + ty * 4 + r;
        float rx = g_rx[b * MDIM + row];
#pragma unroll
        for (int c = 0; c < 4; ++c) {
            int col = n0 + tx * 4 + c;
            float ry = g_ry[b * NDIM + col];
            float v = 1.0f - acc[r][c] * rx * ry;
            costb[(size_t)(row + col) * MDIM + row] = v;   // diag-major
        }
    }
}

// ---------------------------------------------------------------------------
// Kernel 3: forward wavefront, barrier-free skewed warp pipeline.
// R(d-1,·), R(d-2,·) live in registers; i-1 neighbors come via shfl_up.
// Lane 0 takes the cross-warp neighbor from smem mailbox bnd[w-1][d-*],
// prefetched one iteration early (off the critical path).  Warp w waits for
// warp w-1 via an acquire/release progress counter -- no __syncthreads.
// ---------------------------------------------------------------------------
__global__ __launch_bounds__(256) void fwd_kernel(const float* __restrict__ gamma_ptr,
                                                  float* __restrict__ d_out)
{
    __shared__ float bnd[8][NDPAD];    // bnd[w][d] = R(d, 32w+31)
    __shared__ int   prog[8];          // last diag published by warp w

    int w = threadIdx.x >> 5;
    int l = threadIdx.x & 31;
    int i = threadIdx.x;
    int b = blockIdx.x;

    if (threadIdx.x < 8) prog[threadIdx.x] = -1;
    __syncthreads();                   // once, before the pipeline

    float gv  = fmaxf(fabsf(*gamma_ptr), GAMMA_MIN);
    float ig2 = 1.4426950408889634f / gv;
    float gl  = gv * 0.6931471805599453f;

    const float* costb = g_cost + (size_t)b * NDIAG * MDIM;
    float* Rb = g_R + (size_t)b * NDIAG * MDIM;
    float* Sb = g_S + (size_t)b * NDIAG * MDIM;

    float r1 = INFV, r2 = INFV;        // R(d-1, i), R(d-2, i)
    float bndm1 = INFV, bndm2 = INFV;  // R(d-1, 32w-1), R(d-2, 32w-1)

    // cost prefetch ring (4-deep, static slots via unroll-4)
    float creg[4];
#pragma unroll
    for (int u = 0; u < 4; ++u)
        creg[u] = costb[(size_t)u * MDIM + i];

    for (int t = 0; t < 512; t += 4) {
#pragma unroll
        for (int u = 0; u < 4; ++u) {
            int d = t + u;
            int j = d - i;

            float cv = creg[u];
            if (d + 4 < NDIAG)
                creg[u] = costb[(size_t)(d + 4) * MDIM + i];

            // neighbors via shuffle; lane 0 patches in cross-warp values
            float a_im1 = __shfl_up_sync(0xFFFFFFFFu, r2, 1);
            float b_im1 = __shfl_up_sync(0xFFFFFFFFu, r1, 1);
            if (l == 0) { a_im1 = bndm2; b_im1 = bndm1; }

            float a  = (i > 0 && j > 0) ? a_im1
                                        : ((i == 0 && j == 0) ? 0.0f : INFV);
            float bb = (i > 0) ? b_im1 : INFV;
            float cc = (j > 0) ? r1    : INFV;

            float Sv = softmin3(a, bb, cc, ig2, gl);
            float Rv = cv + Sv;

            bool valid = (j >= 0) && (j < NDIM) && (d < NDIAG);
            if (valid) {
                Rb[(size_t)d * MDIM + i] = Rv;
                Sb[(size_t)d * MDIM + i] = Sv;
                if (d == NDIAG - 1)
                    d_out[BATCH * MDIM * NDIM + b] = Rv;   // distance (i==255)
            }

            r2 = r1; r1 = Rv;

            // publish boundary value (lane 31), release progress
            if (l == 31) {
                bnd[w][d] = Rv;
                st_release_cta(&prog[w], d);
            }

            // prefetch next iteration's cross-warp neighbor (lane 0)
            bndm2 = bndm1;
            if (w > 0 && l == 0) {
                while (ld_acquire_cta(&prog[w - 1]) < d) { }
                bndm1 = bnd[w - 1][d];
            }
        }
    }
}

// ---------------------------------------------------------------------------
// Kernel 4: precompute backward weights per cell (fully parallel).
// Zero for invalid cells/neighbors.  Diag 511 is zero padding so bwd can run
// 512 uniform iterations.  w.w carries the E seed: 1 at cell (510, i=255).
// ---------------------------------------------------------------------------
__global__ __launch_bounds__(256) void weights_kernel(const float* __restrict__ gamma_ptr)
{
    int d = blockIdx.x;                // 0..511
    int b = blockIdx.y;
    int i = threadIdx.x;
    int j = d - i;

    float gv = fmaxf(fabsf(*gamma_ptr), GAMMA_MIN);
    float ig = 1.0f / gv;

    const float* Rb = g_R + (size_t)b * NDIAG * MDIM;
    const float* Sb = g_S + (size_t)b * NDIAG * MDIM;

    float4 w = make_float4(0.0f, 0.0f, 0.0f, 0.0f);
    if (d < NDIAG && j >= 0 && j < NDIM) {
        float rc = Rb[(size_t)d * MDIM + i];
        if (i + 1 < MDIM && j + 1 < NDIM)
            w.x = __expf(clamp50((Sb[(size_t)(d + 2) * MDIM + i + 1] - rc) * ig));
        if (i + 1 < MDIM)
            w.y = __expf(clamp50((Sb[(size_t)(d + 1) * MDIM + i + 1] - rc) * ig));
        if (j + 1 < NDIM)
            w.z = __expf(clamp50((Sb[(size_t)(d + 1) * MDIM + i] - rc) * ig));
        if (d == NDIAG - 1 && i == MDIM - 1)
            w.w = 1.0f;                // E(510,255) seed
    }
    g_W[((size_t)b * NDPAD + d) * MDIM + i] = w;
}

// ---------------------------------------------------------------------------
// Kernel 5: backward wavefront, barrier-free skewed warp pipeline (mirrored).
// E(d+1,·), E(d+2,·) in registers; i+1 neighbors via shfl_down; lane 31
// patches from warp w+1's mailbox.  Invalid cells have all-zero weights so
// E computes to exactly 0 outside the matrix -- no validity logic.
//   E(d,i) = E(d+2,i+1)*w.x + E(d+1,i+1)*w.y + E(d+1,i)*w.z + w.w
// ---------------------------------------------------------------------------
__global__ __launch_bounds__(256) void bwd_kernel()
{
    __shared__ float bnd[8][NDPAD];    // bnd[w][d] = E(d, 32w)
    __shared__ int   prog[8];

    int w = threadIdx.x >> 5;
    int l = threadIdx.x & 31;
    int i = threadIdx.x;
    int b = blockIdx.x;

    if (threadIdx.x < 8) prog[threadIdx.x] = 1 << 30;
    __syncthreads();

    const float4* Wb = g_W + (size_t)b * NDPAD * MDIM;
    float* Eb = g_E + (size_t)b * NDIAG * MDIM;

    float e1 = 0.0f, e2 = 0.0f;        // E(d+1, i), E(d+2, i)
    float bndp1 = 0.0f, bndp2 = 0.0f;  // E(d+1, 32w+32), E(d+2, 32w+32)

    // weight prefetch ring: slot u holds diag 511-u initially
    float4 wreg[4];
#pragma unroll
    for (int u = 0; u < 4; ++u)
        wreg[u] = Wb[(size_t)(NDPAD - 1 - u) * MDIM + i];

    for (int t = 0; t < 512; t += 4) {
#pragma unroll
        for (int u = 0; u < 4; ++u) {
            int d = NDPAD - 1 - (t + u);      // 511 down to 0

            float4 w4 = wreg[u];
            if (d - 4 >= 0)
                wreg[u] = Wb[(size_t)(d - 4) * MDIM + i];

            float en  = __shfl_down_sync(0xFFFFFFFFu, e1, 1);  // E(d+1, i+1)
            float e2r = __shfl_down_sync(0xFFFFFFFFu, e2, 1);  // E(d+2, i+1)
            if (l == 31) { en = bndp1; e2r = bndp2; }

            float Ev = fmaf(e2r, w4.x, fmaf(en, w4.y, fmaf(e1, w4.z, w4.w)));

            if (d < NDIAG)
                Eb[(size_t)d * MDIM + i] = Ev;   // coalesced diag-major store

            e2 = e1; e1 = Ev;

            if (l == 0) {
                bnd[w][d] = Ev;
                st_release_cta(&prog[w], d);
            }

            bndp2 = bndp1;
            if (w < 7 && l == 31) {
                while (ld_acquire_cta(&prog[w + 1]) > d) { }
                bndp1 = bnd[w + 1][d];
            }
        }
    }
}

// ---------------------------------------------------------------------------
// Kernel 6: diag-major E -> row-major alignment output.  32x32 output tile
// per block.  Cell (i0+r, j0+c) lives at diag r+c, row-slot r: sm[r+c][r].
// ---------------------------------------------------------------------------
__global__ __launch_bounds__(256) void transpose_kernel(float* __restrict__ out)
{
    __shared__ float sm[63][33];

    int b  = blockIdx.z;
    int i0 = blockIdx.y * 32;
    int j0 = blockIdx.x * 32;
    int d0 = i0 + j0;

    int lane = threadIdx.x & 31;
    int wy   = threadIdx.x >> 5;

    const float* Eb = g_E + (size_t)b * NDIAG * MDIM;

    for (int dl = wy; dl < 63; dl += 8)
        sm[dl][lane] = Eb[(size_t)(d0 + dl) * MDIM + i0 + lane];
    __syncthreads();

    float* outb = out + (size_t)b * MDIM * NDIM;
#pragma unroll
    for (int r = wy; r < 32; r += 8)
        outb[(size_t)(i0 + r) * NDIM + j0 + lane] = sm[r + lane][r];
}

// ---------------------------------------------------------------------------
// Launch.  Inputs: x [8,256,512] f32, y [8,256,512] f32, gamma [] f32.
// Output: alignment [8,256,256] then distance [8], f32.
// ---------------------------------------------------------------------------
extern "C" void kernel_launch(void* const* d_in, const int* in_sizes, int n_in,
                              void* d_out, int out_size)
{
    const float* x     = (const float*)d_in[0];
    const float* y     = (const float*)d_in[1];
    const float* gamma = (const float*)d_in[2];
    float* out = (float*)d_out;

    norms_kernel<<<512, 256>>>(x, y);
    cost_kernel<<<dim3(NDIM / BN, MDIM / BM, BATCH), dim3(16, 16)>>>(x, y);
    fwd_kernel<<<BATCH, 256>>>(gamma, out);
    weights_kernel<<<dim3(NDPAD, BATCH), 256>>>(gamma);
    bwd_kernel<<<BATCH, 256>>>();
    transpose_kernel<<<dim3(8, 8, BATCH), 256>>>(out);
}

// round 13
// speedup vs baseline: 3.4268x; 3.4268x over previous
#include <cuda_runtime.h>
#include <cuda_bf16.h>
#include <math.h>

// Problem constants
#define BATCH 8
#define MDIM 256
#define NDIM 256
#define DDIM 512
#define NDIAG 511            // M + N - 1
#define NDPAD 512
#define INFV 100000000.0f    // matches reference _INF
#define GAMMA_MIN 0.0001f

// ---------------------------------------------------------------------------
// Scratch (static device globals; no allocation)
// layout: diag-major  [b][d][i]  with i = row index (global m), d = m + n
// ---------------------------------------------------------------------------
__device__ float  g_rx[BATCH * MDIM];                 // 1/||x_m||
__device__ float  g_ry[BATCH * NDIM];                 // 1/||y_n||
__device__ float  g_cost[BATCH * NDIAG * MDIM];       // cost, diag-major
__device__ float  g_R[BATCH * NDIAG * MDIM];          // R (interior), diag-major
__device__ float  g_S[BATCH * NDIAG * MDIM];          // softmin value (= R - cost)
__device__ float4 g_W[BATCH * NDPAD * MDIM];          // (wd, wn, wr, 0) per cell
__device__ float  g_E[BATCH * NDIAG * MDIM];          // alignment, diag-major

__device__ __forceinline__ float clamp50(float v)
{
    return fminf(fmaxf(v, -50.0f), 50.0f);
}

__device__ __forceinline__ float ex2_(float x)       // MUFU.EX2
{
    float r;
    asm("ex2.approx.f32 %0, %1;" : "=f"(r) : "f"(x));
    return r;
}
__device__ __forceinline__ float lg2_(float x)       // MUFU.LG2
{
    float r;
    asm("lg2.approx.f32 %0, %1;" : "=f"(r) : "f"(x));
    return r;
}

// softmin_3 via exp2/log2 with folded constants
__device__ __forceinline__ float softmin3(float a, float b, float c,
                                          float ig2, float gl)
{
    float mn = fminf(a, fminf(b, c));
    float s  = ex2_((mn - a) * ig2)
             + ex2_((mn - b) * ig2)
             + ex2_((mn - c) * ig2);
    return mn - gl * lg2_(s);
}

// ---------------------------------------------------------------------------
// Kernel 1: inverse row norms for x and y.  One warp per row.
// ---------------------------------------------------------------------------
__global__ __launch_bounds__(256) void norms_kernel(const float* __restrict__ x,
                                                    const float* __restrict__ y)
{
    int warp = threadIdx.x >> 5;
    int lane = threadIdx.x & 31;
    int row  = blockIdx.x * 8 + warp;

    const float* base;
    float* out;
    if (row < BATCH * MDIM) {
        base = x + (size_t)row * DDIM;
        out  = g_rx + row;
    } else {
        int r = row - BATCH * MDIM;
        base = y + (size_t)r * DDIM;
        out  = g_ry + r;
    }

    const float4* b4 = reinterpret_cast<const float4*>(base);
    float s = 0.0f;
#pragma unroll
    for (int t = 0; t < 4; ++t) {
        float4 v = b4[lane + 32 * t];
        s += v.x * v.x + v.y * v.y + v.z * v.z + v.w * v.w;
    }
#pragma unroll
    for (int o = 16; o; o >>= 1) s += __shfl_xor_sync(0xFFFFFFFFu, s, o);

    if (lane == 0) {
        float n = sqrtf(s);
        n = fmaxf(n, 1e-8f);
        *out = 1.0f / n;
    }
}

// ---------------------------------------------------------------------------
// Kernel 2: cost = 1 - (x.y) * rx * ry, written DIAG-MAJOR.
// ---------------------------------------------------------------------------
#define BM 64
#define BN 64
#define BK 16

__global__ __launch_bounds__(256) void cost_kernel(const float* __restrict__ x,
                                                   const float* __restrict__ y)
{
    __shared__ float Xs[BK][BM + 1];
    __shared__ float Ys[BK][BN + 1];

    int b  = blockIdx.z;
    int m0 = blockIdx.y * BM;
    int n0 = blockIdx.x * BN;
    int tx = threadIdx.x;
    int ty = threadIdx.y;
    int tid = ty * 16 + tx;

    const float* xb = x + ((size_t)b * MDIM + m0) * DDIM;
    const float* yb = y + ((size_t)b * NDIM + n0) * DDIM;

    float acc[4][4];
#pragma unroll
    for (int r = 0; r < 4; ++r)
#pragma unroll
        for (int c = 0; c < 4; ++c) acc[r][c] = 0.0f;

    int kk = tid & 15;
    int rr = tid >> 4;

    for (int k0 = 0; k0 < DDIM; k0 += BK) {
#pragma unroll
        for (int r = 0; r < 4; ++r) {
            Xs[kk][rr + r * 16] = xb[(size_t)(rr + r * 16) * DDIM + k0 + kk];
            Ys[kk][rr + r * 16] = yb[(size_t)(rr + r * 16) * DDIM + k0 + kk];
        }
        __syncthreads();
#pragma unroll
        for (int k = 0; k < BK; ++k) {
            float a[4], bv[4];
#pragma unroll
            for (int r = 0; r < 4; ++r) a[r]  = Xs[k][ty * 4 + r];
#pragma unroll
            for (int c = 0; c < 4; ++c) bv[c] = Ys[k][tx * 4 + c];
#pragma unroll
            for (int r = 0; r < 4; ++r)
#pragma unroll
                for (int c = 0; c < 4; ++c) acc[r][c] += a[r] * bv[c];
        }
        __syncthreads();
    }

    float* costb = g_cost + (size_t)b * NDIAG * MDIM;
#pragma unroll
    for (int r = 0; r < 4; ++r) {
        int row = m0 + ty * 4 + r;
        float rx = g_rx[b * MDIM + row];
#pragma unroll
        for (int c = 0; c < 4; ++c) {
            int col = n0 + tx * 4 + c;
            float ry = g_ry[b * NDIM + col];
            float v = 1.0f - acc[r][c] * rx * ry;
            costb[(size_t)(row + col) * MDIM + row] = v;   // diag-major
        }
    }
}

// ---------------------------------------------------------------------------
// Kernel 3: forward wavefront: registers + shuffles, 2 diagonals per barrier.
// State: r1 = R(dA-1, i), r2 = R(dA-2, i) in registers.  Neighbors i-1/i-2
// via shfl_up(1/2); lanes 0-1 patch from a double-buffered 4-float/warp smem
// boundary array (written by lanes 30-31 of the lower warp last pair).
// Per pair p: cell A (i, dA=2p), halo (i-1, dA), cell B (i, dB=2p+1).
// One __syncthreads per pair (256 barriers total).
// ---------------------------------------------------------------------------
__global__ __launch_bounds__(256) void fwd_kernel(const float* __restrict__ gamma_ptr,
                                                  float* __restrict__ d_out)
{
    // bnd[par][w][0..3] = { r1@lane30, r1@lane31, r2@lane30, r2@lane31 }
    __shared__ float bnd[2][8][4];

    int w = threadIdx.x >> 5;
    int l = threadIdx.x & 31;
    int i = threadIdx.x;
    int b = blockIdx.x;
    int im1 = (i > 0) ? i - 1 : 0;

    if (threadIdx.x < 64)
        ((float*)bnd)[threadIdx.x] = INFV;
    __syncthreads();

    float gv  = fmaxf(fabsf(*gamma_ptr), GAMMA_MIN);
    float ig2 = 1.4426950408889634f / gv;
    float gl  = gv * 0.6931471805599453f;

    const float* costb = g_cost + (size_t)b * NDIAG * MDIM;
    float* Rb = g_R + (size_t)b * NDIAG * MDIM;
    float* Sb = g_S + (size_t)b * NDIAG * MDIM;

    float r1 = INFV, r2 = INFV;

    // cost prefetch rings (4 pairs deep = 8 diagonals of lookahead)
    float cA[4], cB[4], cH[4];
#pragma unroll
    for (int u = 0; u < 4; ++u) {
        int dA = 2 * u, dB = dA + 1;
        cA[u] = costb[(size_t)dA * MDIM + i];
        cB[u] = costb[(size_t)dB * MDIM + i];
        cH[u] = costb[(size_t)dA * MDIM + im1];
    }

    for (int t = 0; t < 256; t += 4) {
#pragma unroll
        for (int u = 0; u < 4; ++u) {
            int p  = t + u;
            int dA = 2 * p;
            int dB = dA + 1;
            int j  = dA - i;
            int j1 = j + 1;
            const int par = u & 1;          // p parity (t multiple of 4)

            float cvA = cA[u], cvB = cB[u], cvH = cH[u];
            {
                int dA2 = dA + 8, dB2 = dA2 + 1;
                if (dA2 < NDIAG) {
                    cA[u] = costb[(size_t)dA2 * MDIM + i];
                    cH[u] = costb[(size_t)dA2 * MDIM + im1];
                }
                if (dB2 < NDIAG)
                    cB[u] = costb[(size_t)dB2 * MDIM + i];
            }

            // neighbors via shuffle; lanes 0-1 patch from boundary smem
            float r1u1 = __shfl_up_sync(0xFFFFFFFFu, r1, 1);
            float r2u1 = __shfl_up_sync(0xFFFFFFFFu, r2, 1);
            float r1u2 = __shfl_up_sync(0xFFFFFFFFu, r1, 2);
            float r2u2 = __shfl_up_sync(0xFFFFFFFFu, r2, 2);
            if (l == 0) {
                r1u1 = (w > 0) ? bnd[par][w - 1][1] : INFV;
                r2u1 = (w > 0) ? bnd[par][w - 1][3] : INFV;
                r1u2 = (w > 0) ? bnd[par][w - 1][0] : INFV;
                r2u2 = (w > 0) ? bnd[par][w - 1][2] : INFV;
            }
            if (l == 1) {
                r1u2 = (w > 0) ? bnd[par][w - 1][1] : INFV;
                r2u2 = (w > 0) ? bnd[par][w - 1][3] : INFV;
            }

            // ---- cell A (i, dA) ----
            float a  = (i > 0 && j > 0) ? r2u1
                                        : ((i == 0 && j == 0) ? 0.0f : INFV);
            float bb = (i > 0) ? r1u1 : INFV;
            float cc = (j > 0) ? r1   : INFV;
            float SvA = softmin3(a, bb, cc, ig2, gl);
            float RvA = cvA + SvA;

            // ---- halo cell (i-1, dA), its j = j1 ----
            float a_h = (i > 1 && j1 > 0) ? r2u2
                                          : ((i == 1 && j1 == 0) ? 0.0f : INFV);
            float b_h = (i > 1) ? r1u2 : INFV;
            float c_h = (j1 > 0) ? r1u1 : INFV;
            float RvH = cvH + softmin3(a_h, b_h, c_h, ig2, gl);

            // ---- cell B (i, dB) from registers ----
            float a1 = (i > 0 && j1 > 0) ? r1u1 : INFV;
            float b1 = (i > 0) ? RvH : INFV;
            float c1 = (j1 > 0) ? RvA : INFV;
            float SvB = softmin3(a1, b1, c1, ig2, gl);
            float RvB = cvB + SvB;

            bool validA = (j  >= 0) && (j  < NDIM);
            bool validB = (j1 >= 0) && (j1 < NDIM) && (dB < NDIAG);

            if (validA) {
                Rb[(size_t)dA * MDIM + i] = RvA;
                Sb[(size_t)dA * MDIM + i] = SvA;
                if (dA == NDIAG - 1)
                    d_out[BATCH * MDIM * NDIM + b] = RvA;   // distance (i==255)
            }
            if (validB) {
                Rb[(size_t)dB * MDIM + i] = RvB;
                Sb[(size_t)dB * MDIM + i] = SvB;
            }

            // advance register state: r1 = R(dB, i), r2 = R(dA, i)
            r2 = RvA;
            r1 = RvB;

            // publish boundary values for the next pair (lanes 30, 31)
            if (l >= 30) {
                int idx = l - 30;
                bnd[par ^ 1][w][idx]     = r1;
                bnd[par ^ 1][w][2 + idx] = r2;
            }
            __syncthreads();
        }
    }
}

// ---------------------------------------------------------------------------
// Kernel 4: precompute backward weights per cell (fully parallel).
// Zero for invalid cells/neighbors -> bwd needs no validity logic at all.
// ---------------------------------------------------------------------------
__global__ __launch_bounds__(256) void weights_kernel(const float* __restrict__ gamma_ptr)
{
    int d = blockIdx.x;                // 0..510
    int b = blockIdx.y;
    int i = threadIdx.x;
    int j = d - i;

    float gv = fmaxf(fabsf(*gamma_ptr), GAMMA_MIN);
    float ig = 1.0f / gv;

    const float* Rb = g_R + (size_t)b * NDIAG * MDIM;
    const float* Sb = g_S + (size_t)b * NDIAG * MDIM;

    float4 w = make_float4(0.0f, 0.0f, 0.0f, 0.0f);
    if (j >= 0 && j < NDIM) {
        float rc = Rb[(size_t)d * MDIM + i];
        if (i + 1 < MDIM && j + 1 < NDIM)
            w.x = __expf(clamp50((Sb[(size_t)(d + 2) * MDIM + i + 1] - rc) * ig));
        if (i + 1 < MDIM)
            w.y = __expf(clamp50((Sb[(size_t)(d + 1) * MDIM + i + 1] - rc) * ig));
        if (j + 1 < NDIM)
            w.z = __expf(clamp50((Sb[(size_t)(d + 1) * MDIM + i] - rc) * ig));
    }
    g_W[((size_t)b * NDPAD + d) * MDIM + i] = w;
}

// ---------------------------------------------------------------------------
// Kernel 5: backward wavefront: registers + shuffles, 2 diagonals per barrier.
// State: e1 = E(dA+1, i), e2 = E(dA+2, i).  Neighbors i+1/i+2 via shfl_down;
// lanes 30-31 patch from warp w+1's boundary (lanes 0-1), zeros past row 255.
// Pair p: dA = 509-2p (odd), dB = dA-1.
//   EvA = e2[i+1]*wA.x + e1[i+1]*wA.y + e1[i]*wA.z
//   EvH = e2[i+2]*wH.x + e1[i+2]*wH.y + e1[i+1]*wH.z       (halo i+1, dA)
//   EvB = e1[i+1]*wB.x + EvH*wB.y + EvA*wB.z
// Invalid cells have all-zero weights -> no validity logic.
// ---------------------------------------------------------------------------
__global__ __launch_bounds__(256) void bwd_kernel()
{
    // bnd[par][w][0..3] = { e1@lane0, e1@lane1, e2@lane0, e2@lane1 }
    __shared__ float bnd[2][8][4];

    int w = threadIdx.x >> 5;
    int l = threadIdx.x & 31;
    int i = threadIdx.x;
    int b = blockIdx.x;
    int ip1 = (i < MDIM - 1) ? i + 1 : MDIM - 1;

    if (threadIdx.x < 64)
        ((float*)bnd)[threadIdx.x] = 0.0f;
    __syncthreads();

    const float4* Wb = g_W + (size_t)b * NDPAD * MDIM;
    float* Eb = g_E + (size_t)b * NDIAG * MDIM;

    float e1 = (i == MDIM - 1) ? 1.0f : 0.0f;   // E(510, i) seed
    float e2 = 0.0f;                             // E(511, i) = 0
    Eb[(size_t)(NDIAG - 1) * MDIM + i] = e1;

    // weight prefetch rings (4 pairs deep)
    float4 wA[4], wBv[4], wH[4];
#pragma unroll
    for (int u = 0; u < 4; ++u) {
        int dA = NDIAG - 2 - 2 * u, dB = dA - 1;     // 509, 507, 505, 503
        wA[u]  = Wb[(size_t)dA * MDIM + i];
        wBv[u] = Wb[(size_t)dB * MDIM + i];
        wH[u]  = Wb[(size_t)dA * MDIM + ip1];
    }

    for (int t = 0; t < 256; t += 4) {
#pragma unroll
        for (int u = 0; u < 4; ++u) {
            int p  = t + u;
            int dA = NDIAG - 2 - 2 * p;       // 509 .. 1, then -1 (pad pair)
            int dB = dA - 1;
            const int par = u & 1;

            float4 a4 = wA[u], b4 = wBv[u], h4 = wH[u];
            {
                int dA2 = dA - 8, dB2 = dA2 - 1;
                if (dA2 >= 0) {
                    wA[u] = Wb[(size_t)dA2 * MDIM + i];
                    wH[u] = Wb[(size_t)dA2 * MDIM + ip1];
                }
                if (dB2 >= 0)
                    wBv[u] = Wb[(size_t)dB2 * MDIM + i];
            }

            float e1d1 = __shfl_down_sync(0xFFFFFFFFu, e1, 1);
            float e2d1 = __shfl_down_sync(0xFFFFFFFFu, e2, 1);
            float e1d2 = __shfl_down_sync(0xFFFFFFFFu, e1, 2);
            float e2d2 = __shfl_down_sync(0xFFFFFFFFu, e2, 2);
            if (l == 31) {
                e1d1 = (w < 7) ? bnd[par][w + 1][0] : 0.0f;
                e2d1 = (w < 7) ? bnd[par][w + 1][2] : 0.0f;
                e1d2 = (w < 7) ? bnd[par][w + 1][1] : 0.0f;
                e2d2 = (w < 7) ? bnd[par][w + 1][3] : 0.0f;
            }
            if (l == 30) {
                e1d2 = (w < 7) ? bnd[par][w + 1][0] : 0.0f;
                e2d2 = (w < 7) ? bnd[par][w + 1][2] : 0.0f;
            }

            float EvA = fmaf(e2d1, a4.x, fmaf(e1d1, a4.y, e1 * a4.z));
            float EvH = fmaf(e2d2, h4.x, fmaf(e1d2, h4.y, e1d1 * h4.z));
            float EvB = fmaf(e1d1, b4.x, fmaf(EvH, b4.y, EvA * b4.z));

            if (dA >= 0) {
                Eb[(size_t)dA * MDIM + i] = EvA;
                Eb[(size_t)dB * MDIM + i] = EvB;
            }

            // advance: e1 = E(dB, i), e2 = E(dA, i)
            e2 = EvA;
            e1 = EvB;

            if (l < 2) {
                bnd[par ^ 1][w][l]     = e1;
                bnd[par ^ 1][w][2 + l] = e2;
            }
            __syncthreads();
        }
    }
}

// ---------------------------------------------------------------------------
// Kernel 6: diag-major E -> row-major alignment output.  32x32 output tile
// per block.  Cell (i0+r, j0+c) lives at diag r+c, row-slot r: sm[r+c][r].
// ---------------------------------------------------------------------------
__global__ __launch_bounds__(256) void transpose_kernel(float* __restrict__ out)
{
    __shared__ float sm[63][33];

    int b  = blockIdx.z;
    int i0 = blockIdx.y * 32;
    int j0 = blockIdx.x * 32;
    int d0 = i0 + j0;

    int lane = threadIdx.x & 31;
    int wy   = threadIdx.x >> 5;

    const float* Eb = g_E + (size_t)b * NDIAG * MDIM;

    for (int dl = wy; dl < 63; dl += 8)
        sm[dl][lane] = Eb[(size_t)(d0 + dl) * MDIM + i0 + lane];
    __syncthreads();

    float* outb = out + (size_t)b * MDIM * NDIM;
#pragma unroll
    for (int r = wy; r < 32; r += 8)
        outb[(size_t)(i0 + r) * NDIM + j0 + lane] = sm[r + lane][r];
}

// ---------------------------------------------------------------------------
// Launch.  Inputs: x [8,256,512] f32, y [8,256,512] f32, gamma [] f32.
// Output: alignment [8,256,256] then distance [8], f32.
// ---------------------------------------------------------------------------
extern "C" void kernel_launch(void* const* d_in, const int* in_sizes, int n_in,
                              void* d_out, int out_size)
{
    const float* x     = (const float*)d_in[0];
    const float* y     = (const float*)d_in[1];
    const float* gamma = (const float*)d_in[2];
    float* out = (float*)d_out;

    norms_kernel<<<512, 256>>>(x, y);
    cost_kernel<<<dim3(NDIM / BN, MDIM / BM, BATCH), dim3(16, 16)>>>(x, y);
    fwd_kernel<<<BATCH, 256>>>(gamma, out);
    weights_kernel<<<dim3(NDIAG, BATCH), 256>>>(gamma);
    bwd_kernel<<<BATCH, 256>>>();
    transpose_kernel<<<dim3(8, 8, BATCH), 256>>>(out);
}